// round 3
// baseline (speedup 1.0000x reference)
#include <cuda_runtime.h>

#define B_   128
#define S_   512
#define D_   256
#define H_   512
#define ODIM 1275

typedef unsigned long long u64;

// ---------------- persistent device scratch ----------------
__device__ __align__(16) float g_xT[S_ * D_ * B_];        // [t][d][b]
__device__ __align__(16) float g_W0p[128 * 768 * 16];     // [jtile][k][c], c = jj*4+gate
__device__ __align__(16) float g_W1p[128 * 1024 * 16];
__device__ __align__(16) float g_h0[2][H_ * B_];          // [buf][j][b]
__device__ __align__(16) float g_h1[2][H_ * B_];
__device__ unsigned g_bar_cnt = 0;
__device__ volatile unsigned g_bar_gen = 0;

// ---------------- f32x2 helpers ----------------
__device__ __forceinline__ u64 pk2(float x, float y) {
    u64 r; asm("mov.b64 %0, {%1, %2};" : "=l"(r) : "f"(x), "f"(y)); return r;
}
__device__ __forceinline__ float2 up2(u64 v) {
    float2 r; asm("mov.b64 {%0, %1}, %2;" : "=f"(r.x), "=f"(r.y) : "l"(v)); return r;
}
__device__ __forceinline__ u64 add2(u64 a, u64 b) {
    u64 r; asm("add.rn.f32x2 %0, %1, %2;" : "=l"(r) : "l"(a), "l"(b)); return r;
}
#define FMA2(acc, a, b) asm("fma.rn.f32x2 %0, %1, %2, %0;" : "+l"(acc) : "l"(a), "l"(b))

// ---------------- cp.async ----------------
__device__ __forceinline__ void cp16(float4* dst, const float4* src) {
    unsigned d = (unsigned)__cvta_generic_to_shared(dst);
    asm volatile("cp.async.cg.shared.global [%0], [%1], 16;\n" :: "r"(d), "l"(src));
}
__device__ __forceinline__ void cp_commit() { asm volatile("cp.async.commit_group;\n" ::); }
__device__ __forceinline__ void cp_wait0()  { asm volatile("cp.async.wait_group 0;\n" ::); }

// ---------------- grid-wide barrier (all CTAs resident) ----------------
__device__ __forceinline__ void grid_sync(unsigned G) {
    __syncthreads();
    if (threadIdx.x == 0) {
        __threadfence();
        unsigned gen = g_bar_gen;
        if (atomicAdd(&g_bar_cnt, 1u) == G - 1u) {
            g_bar_cnt = 0;
            __threadfence();
            g_bar_gen = gen + 1u;
        } else {
            while (g_bar_gen == gen) { }
            __threadfence();
        }
    }
    __syncthreads();
}

// ---------------- prep: transpose x, pack weights per jtile ----------------
__global__ void prep_kernel(const float* __restrict__ x,
                            const float* __restrict__ W0,
                            const float* __restrict__ W1)
{
    const int stride = gridDim.x * blockDim.x;
    const int tid0 = blockIdx.x * blockDim.x + threadIdx.x;

    for (int idx = tid0; idx < S_ * D_ * B_; idx += stride) {
        int t = idx / (D_ * B_);
        int d = (idx / B_) % B_ ? 0 : 0, dd = (idx / B_) % D_;
        int b = idx % B_;
        (void)d;
        g_xT[idx] = x[(b * S_ + t) * D_ + dd];
    }
    for (int idx = tid0; idx < 128 * 768 * 16; idx += stride) {
        int jt = idx / (768 * 16);
        int k  = (idx >> 4) % 768;
        int c  = idx & 15;
        g_W0p[idx] = W0[k * 2048 + (c & 3) * 512 + jt * 4 + (c >> 2)];
    }
    for (int idx = tid0; idx < 128 * 1024 * 16; idx += stride) {
        int jt = idx / (1024 * 16);
        int k  = (idx >> 4) % 1024;
        int c  = idx & 15;
        g_W1p[idx] = W1[k * 2048 + (c & 3) * 512 + jt * 4 + (c >> 2)];
    }
}

// ---------------- activation chunk prefetch (64 k-rows x 128 b) ----------------
// smem layout per row k: float4 position = (q & 1)*16 + (q >> 1), q = batch quad.
// => a thread's 8 batches (quads 2bt, 2bt+1) sit at [k*32 + bt] and [k*32 + 16 + bt],
//    giving 128B-contiguous warp reads (1 wavefront per LDS.128).
__device__ __forceinline__ void prefetch_chunk(
    float4* s_act4, const float4* srcA, const float4* srcB, bool zeroB,
    int ch, int xch, int tid)
{
    float4* dst = s_act4 + ((ch & 1) << 11);
    #pragma unroll
    for (int i = 0; i < 4; i++) {
        int idx = tid + (i << 9);              // 0..2047
        int k = idx >> 5;
        int q = idx & 31;
        int dpos = (k << 5) + ((q & 1) << 4) + (q >> 1);
        if (ch < xch) {
            cp16(dst + dpos, srcA + ((size_t)ch << 11) + idx);
        } else if (zeroB) {
            dst[dpos] = make_float4(0.f, 0.f, 0.f, 0.f);
        } else {
            cp16(dst + dpos, srcB + ((size_t)(ch - xch) << 11) + idx);
        }
    }
}

// ---------------- fused GEMM (FFMA2, K-split 8) + gates ----------------
// 512 threads = 8 ksplit x (16 bt x 4 ct). Thread tile: 8 batches x 4 gates of
// hidden unit j0+ct. Acc: 16 u64 = acc[gate*4 + bpair].
__device__ __forceinline__ void do_phase(
    const float4* __restrict__ srcA, const float4* __restrict__ srcB, bool zeroB,
    int nch, int xch,
    const float4* __restrict__ s_w4,
    float4* s_act4, float* cstate, float* __restrict__ hout,
    const float* __restrict__ bias,
    int tid, int ks, int r, int bt, int ct, int j0)
{
    u64 acc[16];
    #pragma unroll
    for (int i = 0; i < 16; i++) acc[i] = 0ull;

    prefetch_chunk(s_act4, srcA, srcB, zeroB, 0, xch, tid);
    cp_commit();

    for (int ch = 0; ch < nch; ch++) {
        cp_wait0();
        __syncthreads();
        if (ch + 1 < nch) {
            prefetch_chunk(s_act4, srcA, srcB, zeroB, ch + 1, xch, tid);
            cp_commit();
        }
        const float4* ab = s_act4 + ((ch & 1) << 11);
        const int kbase = ch << 6;
        #pragma unroll
        for (int u = 0; u < 8; u++) {
            const int k = (u << 3) | ks;
            float4 a0q = ab[(k << 5) + bt];          // quads 2bt   (batches 8bt..8bt+3)
            float4 a1q = ab[(k << 5) + 16 + bt];     // quads 2bt+1 (batches 8bt+4..8bt+7)
            float4 wq  = s_w4[((kbase + k) << 2) + ct];
            u64 p0 = pk2(a0q.x, a0q.y), p1 = pk2(a0q.z, a0q.w);
            u64 p2 = pk2(a1q.x, a1q.y), p3 = pk2(a1q.z, a1q.w);
            u64 s0 = pk2(wq.x, wq.x), s1 = pk2(wq.y, wq.y);
            u64 s2 = pk2(wq.z, wq.z), s3 = pk2(wq.w, wq.w);
            FMA2(acc[0],  p0, s0); FMA2(acc[1],  p1, s0); FMA2(acc[2],  p2, s0); FMA2(acc[3],  p3, s0);
            FMA2(acc[4],  p0, s1); FMA2(acc[5],  p1, s1); FMA2(acc[6],  p2, s1); FMA2(acc[7],  p3, s1);
            FMA2(acc[8],  p0, s2); FMA2(acc[9],  p1, s2); FMA2(acc[10], p2, s2); FMA2(acc[11], p3, s2);
            FMA2(acc[12], p0, s3); FMA2(acc[13], p1, s3); FMA2(acc[14], p2, s3); FMA2(acc[15], p3, s3);
        }
    }
    __syncthreads();   // all compute on act buffers done before partials overwrite them

    // ---- K-split partials, slot-major conflict-free layout: [slot][ks*64 + r] ----
    {
        u64* pb = (u64*)s_act4;
        const int row = (ks << 6) + r;   // 0..511
        #pragma unroll
        for (int s = 0; s < 16; s++) pb[s * 513 + row] = acc[s];
    }
    __syncthreads();

    // ---- reduce across 8 ksplits + gate math (256 active threads) ----
    if (tid < 256) {
        const int rq  = tid & 63;
        const int p   = tid >> 6;        // 0..3: batch pair within thread tile
        const int btq = rq >> 2;
        const int ctq = rq & 3;
        const u64* pb = (const u64*)s_act4;

        u64 z[4];
        #pragma unroll
        for (int c = 0; c < 4; c++) {
            const u64* col = pb + (c * 4 + p) * 513 + rq;
            u64 s = col[0];
            #pragma unroll
            for (int kk = 1; kk < 8; kk++) s = add2(s, col[kk * 64]);
            z[c] = s;
        }
        const int j = j0 + ctq;
        const float bi = bias[j];
        const float bf = bias[H_ + j];
        const float bg = bias[2 * H_ + j];
        const float bo = bias[3 * H_ + j];
        float2 zi = up2(z[0]), zf = up2(z[1]), zg = up2(z[2]), zo = up2(z[3]);

        const int b0 = (btq << 3) + (p << 1);
        float* cs = cstate + ctq * 128 + b0;

        float siA = 1.f / (1.f + expf(-(zi.x + bi)));
        float sfA = 1.f / (1.f + expf(-(zf.x + bf)));
        float tgA = tanhf(zg.x + bg);
        float soA = 1.f / (1.f + expf(-(zo.x + bo)));
        float cnA = sfA * cs[0] + siA * tgA;
        cs[0] = cnA;
        float hA = soA * tanhf(cnA);

        float siB = 1.f / (1.f + expf(-(zi.y + bi)));
        float sfB = 1.f / (1.f + expf(-(zf.y + bf)));
        float tgB = tanhf(zg.y + bg);
        float soB = 1.f / (1.f + expf(-(zo.y + bo)));
        float cnB = sfB * cs[1] + siB * tgB;
        cs[1] = cnB;
        float hB = soB * tanhf(cnB);

        *(float2*)(hout + j * 128 + b0) = make_float2(hA, hB);
    }
    __syncthreads();
}

// ---------------- persistent main kernel: 128 CTAs x 512 threads ----------------
__global__ void __launch_bounds__(512, 1)
lstm_main(const float* __restrict__ b0g,
          const float* __restrict__ b1g,
          const float* __restrict__ Wp,
          const float* __restrict__ bp,
          float* __restrict__ out)
{
    extern __shared__ float smem[];
    float* s_w0  = smem;                    // 768*16   = 12288 floats
    float* s_w1  = s_w0 + 768 * 16;         // 1024*16  = 16384 floats
    float* s_act = s_w1 + 1024 * 16;        // 16448 floats (staging 16384 + pad for partials)
    float* s_c0  = s_act + 16448;           // 512
    float* s_c1  = s_c0 + 512;              // 512
    // total = 12288+16384+16448+512+512 = 46144 floats = 184576 bytes

    const int tid = threadIdx.x;
    const unsigned G = gridDim.x;
    const int jt = blockIdx.x;
    const int j0 = jt * 4;
    const int ks = tid >> 6;     // 0..7
    const int r  = tid & 63;
    const int bt = r >> 2;       // 0..15
    const int ct = r & 3;        // 0..3

    // preload packed weights into smem (resident for entire kernel)
    {
        const float4* w0s = (const float4*)g_W0p + (size_t)jt * 768 * 4;
        const float4* w1s = (const float4*)g_W1p + (size_t)jt * 1024 * 4;
        float4* d0 = (float4*)s_w0;
        float4* d1 = (float4*)s_w1;
        for (int i = tid; i < 768 * 4; i += 512) d0[i] = w0s[i];
        for (int i = tid; i < 1024 * 4; i += 512) d1[i] = w1s[i];
    }
    for (int i = tid; i < 512; i += 512) { s_c0[i] = 0.f; s_c1[i] = 0.f; }
    __syncthreads();

    float4* s_act4 = (float4*)s_act;
    const float4* s_w04 = (const float4*)s_w0;
    const float4* s_w14 = (const float4*)s_w1;

    for (int t = 0; t < S_; t++) {
        const int cur = t & 1, prv = cur ^ 1;

        // L0: act = [x_t (256 rows) | h0_prev (512 rows)], 12 chunks (4 from x)
        do_phase((const float4*)(g_xT + (size_t)t * D_ * B_),
                 (const float4*)g_h0[prv], t == 0, 12, 4,
                 s_w04, s_act4, s_c0, g_h0[cur], b0g,
                 tid, ks, r, bt, ct, j0);

        grid_sync(G);   // h0(t) visible to all CTAs

        // L1: act = [h0_cur (512) | h1_prev (512)], 16 chunks (8 from h0)
        do_phase((const float4*)g_h0[cur],
                 (const float4*)g_h1[prv], t == 0, 16, 8,
                 s_w14, s_act4, s_c1, g_h1[cur], b1g,
                 tid, ks, r, bt, ct, j0);
        // next step's L0 grid_sync orders L1(t) -> L1(t+1)
    }

    grid_sync(G);

    // ---- projection: out[b][m] = sum_k h1T[k][b] * Wp[k][m] + bp[m] ----
    {
        const float* h1f = g_h1[1];   // t = 511 -> cur = 1
        int mstart = jt * 10;
        int mend = mstart + 10; if (mend > ODIM) mend = ODIM;
        int b  = tid & 127;
        int mq = tid >> 7;           // 0..3
        for (int m = mstart + mq; m < mend; m += 4) {
            float acc = bp[m];
            #pragma unroll 4
            for (int k = 0; k < H_; k += 4) {
                acc += h1f[(k + 0) * 128 + b] * Wp[(k + 0) * ODIM + m];
                acc += h1f[(k + 1) * 128 + b] * Wp[(k + 1) * ODIM + m];
                acc += h1f[(k + 2) * 128 + b] * Wp[(k + 2) * ODIM + m];
                acc += h1f[(k + 3) * 128 + b] * Wp[(k + 3) * ODIM + m];
            }
            out[b * ODIM + m] = acc;
        }
    }
}

// ---------------- entry ----------------
extern "C" void kernel_launch(void* const* d_in, const int* in_sizes, int n_in,
                              void* d_out, int out_size)
{
    const float* x  = (const float*)d_in[0];
    const float* W0 = (const float*)d_in[1];
    const float* b0 = (const float*)d_in[2];
    const float* W1 = (const float*)d_in[3];
    const float* b1 = (const float*)d_in[4];
    const float* Wp = (const float*)d_in[5];
    const float* bp = (const float*)d_in[6];
    float* out = (float*)d_out;

    cudaFuncSetAttribute(lstm_main, cudaFuncAttributeMaxDynamicSharedMemorySize, 184576);

    prep_kernel<<<2048, 256>>>(x, W0, W1);
    lstm_main<<<128, 512, 184576>>>(b0, b1, Wp, bp, out);
}

// round 4
// speedup vs baseline: 1.8104x; 1.8104x over previous
#include <cuda_runtime.h>

#define B_   128
#define S_   512
#define D_   256
#define H_   512
#define ODIM 1275

typedef unsigned long long u64;

// ---------------- persistent device scratch ----------------
__device__ __align__(16) float g_xT[S_ * D_ * B_];        // [t][d][b]
__device__ __align__(16) float g_W0p[128 * 768 * 16];     // [jtile][k][c], c = jj*4+gate
__device__ __align__(16) float g_W1p[128 * 1024 * 16];
__device__ __align__(16) float g_h0[2][H_ * B_];          // [buf][j][b]
__device__ __align__(16) float g_h1[2][H_ * B_];
__device__ unsigned g_bar_cnt = 0;
__device__ volatile unsigned g_bar_gen = 0;

// ---------------- f32x2 / fast-math helpers ----------------
__device__ __forceinline__ u64 pk2(float x, float y) {
    u64 r; asm("mov.b64 %0, {%1, %2};" : "=l"(r) : "f"(x), "f"(y)); return r;
}
__device__ __forceinline__ float2 up2(u64 v) {
    float2 r; asm("mov.b64 {%0, %1}, %2;" : "=f"(r.x), "=f"(r.y) : "l"(v)); return r;
}
__device__ __forceinline__ u64 add2(u64 a, u64 b) {
    u64 r; asm("add.rn.f32x2 %0, %1, %2;" : "=l"(r) : "l"(a), "l"(b)); return r;
}
#define FMA2(acc, a, b) asm("fma.rn.f32x2 %0, %1, %2, %0;" : "+l"(acc) : "l"(a), "l"(b))

__device__ __forceinline__ float ex2f(float x) {
    float y; asm("ex2.approx.ftz.f32 %0, %1;" : "=f"(y) : "f"(x)); return y;
}
__device__ __forceinline__ float rcpf(float x) {
    float y; asm("rcp.approx.ftz.f32 %0, %1;" : "=f"(y) : "f"(x)); return y;
}
// sigmoid(z) = 1/(1+2^(-z*log2e))
__device__ __forceinline__ float fsig(float z) {
    return rcpf(1.f + ex2f(-1.44269504088896f * z));
}
// tanh(z) = 1 - 2/(e^{2z}+1); saturates correctly at +-inf of exp
__device__ __forceinline__ float ftanh(float z) {
    return 1.f - 2.f * rcpf(1.f + ex2f(2.88539008177793f * z));
}

// ---------------- cp.async ----------------
__device__ __forceinline__ void cp16(float4* dst, const float4* src) {
    unsigned d = (unsigned)__cvta_generic_to_shared(dst);
    asm volatile("cp.async.cg.shared.global [%0], [%1], 16;\n" :: "r"(d), "l"(src));
}
__device__ __forceinline__ void cp_commit() { asm volatile("cp.async.commit_group;\n" ::); }
__device__ __forceinline__ void cp_wait0()  { asm volatile("cp.async.wait_group 0;\n" ::); }

// ---------------- grid-wide barrier (all CTAs resident) ----------------
__device__ __forceinline__ void grid_sync(unsigned G) {
    __syncthreads();
    if (threadIdx.x == 0) {
        __threadfence();
        unsigned gen = g_bar_gen;
        if (atomicAdd(&g_bar_cnt, 1u) == G - 1u) {
            g_bar_cnt = 0;
            __threadfence();
            g_bar_gen = gen + 1u;
        } else {
            while (g_bar_gen == gen) { }
            __threadfence();
        }
    }
    __syncthreads();
}

// ---------------- prep: transpose x, pack weights per jtile ----------------
__global__ void prep_kernel(const float* __restrict__ x,
                            const float* __restrict__ W0,
                            const float* __restrict__ W1)
{
    const int stride = gridDim.x * blockDim.x;
    const int tid0 = blockIdx.x * blockDim.x + threadIdx.x;

    for (int idx = tid0; idx < S_ * D_ * B_; idx += stride) {
        int t = idx / (D_ * B_);
        int d = (idx / B_) % D_;
        int b = idx % B_;
        g_xT[idx] = x[(b * S_ + t) * D_ + d];
    }
    for (int idx = tid0; idx < 128 * 768 * 16; idx += stride) {
        int jt = idx / (768 * 16);
        int k  = (idx >> 4) % 768;
        int c  = idx & 15;
        g_W0p[idx] = W0[k * 2048 + (c & 3) * 512 + jt * 4 + (c >> 2)];
    }
    for (int idx = tid0; idx < 128 * 1024 * 16; idx += stride) {
        int jt = idx / (1024 * 16);
        int k  = (idx >> 4) % 1024;
        int c  = idx & 15;
        g_W1p[idx] = W1[k * 2048 + (c & 3) * 512 + jt * 4 + (c >> 2)];
    }
}

// ---------------- activation chunk prefetch (64 k-rows x 128 b, linear) ----------------
__device__ __forceinline__ void prefetch_chunk(
    float4* s_act4, const float4* srcA, const float4* srcB, bool zeroB,
    int ch, int xch, int tid)
{
    float4* dst = s_act4 + ((ch & 1) << 11);
    if (ch < xch) {
        const float4* s = srcA + ((size_t)ch << 11);
        #pragma unroll
        for (int i = 0; i < 8; i++) { int idx = tid + (i << 8); cp16(dst + idx, s + idx); }
    } else if (zeroB) {
        float4 zz = make_float4(0.f, 0.f, 0.f, 0.f);
        #pragma unroll
        for (int i = 0; i < 8; i++) { int idx = tid + (i << 8); dst[idx] = zz; }
    } else {
        const float4* s = srcB + ((size_t)(ch - xch) << 11);
        #pragma unroll
        for (int i = 0; i < 8; i++) { int idx = tid + (i << 8); cp16(dst + idx, s + idx); }
    }
}

// ---------------- fused GEMM (FFMA2, K-split 2) + gates ----------------
// 256 threads = 2 ksplit x (16 bt x 8 ct). Thread tile: 8 batches x 2 cols.
// acc[a], a = q*2+cc: u64 = (z[8bt+2q], z[8bt+2q+1]) for col 2ct+cc.
__device__ __forceinline__ void do_phase(
    const float4* __restrict__ srcA, const float4* __restrict__ srcB, bool zeroB,
    int nch, int xch,
    const u64* __restrict__ s_w64,
    float4* s_act4, float* cstate, float* __restrict__ hout,
    const float* __restrict__ bias,
    int tid, int ks, int r, int bt, int ct, int j0)
{
    u64 acc[8];
    #pragma unroll
    for (int i = 0; i < 8; i++) acc[i] = 0ull;

    prefetch_chunk(s_act4, srcA, srcB, zeroB, 0, xch, tid);
    cp_commit();

    for (int ch = 0; ch < nch; ch++) {
        cp_wait0();
        __syncthreads();
        if (ch + 1 < nch) {
            prefetch_chunk(s_act4, srcA, srcB, zeroB, ch + 1, xch, tid);
            cp_commit();
        }
        const float4* ab = s_act4 + ((ch & 1) << 11);
        const u64* wt = s_w64 + ((size_t)(ch << 6) << 3);

        // software pipeline over 32 k-steps (k = 2u + ks)
        float4 A0 = ab[(ks << 5) + (bt << 1)];
        float4 A1 = ab[(ks << 5) + (bt << 1) + 1];
        u64 W = wt[(ks << 3) + ct];
        #pragma unroll
        for (int u = 0; u < 32; u++) {
            float4 B0, B1; u64 V;
            if (u < 31) {
                const int kn = ((u + 1) << 1) | ks;
                B0 = ab[(kn << 5) + (bt << 1)];
                B1 = ab[(kn << 5) + (bt << 1) + 1];
                V  = wt[(kn << 3) + ct];
            }
            float2 wv = up2(W);
            u64 s0 = pk2(wv.x, wv.x);
            u64 s1 = pk2(wv.y, wv.y);
            u64 p0 = pk2(A0.x, A0.y), p1 = pk2(A0.z, A0.w);
            u64 p2 = pk2(A1.x, A1.y), p3 = pk2(A1.z, A1.w);
            FMA2(acc[0], p0, s0); FMA2(acc[1], p0, s1);
            FMA2(acc[2], p1, s0); FMA2(acc[3], p1, s1);
            FMA2(acc[4], p2, s0); FMA2(acc[5], p2, s1);
            FMA2(acc[6], p3, s0); FMA2(acc[7], p3, s1);
            A0 = B0; A1 = B1; W = V;
        }
    }
    // acc[q*2+cc] holds (z[8bt+2q], z[8bt+2q+1]) for col 2ct+cc? NOTE: with the
    // FMA ordering above, acc index a = q*2 + cc where q from p0..p3 order:
    // p0->(b+0,b+1), p1->(b+2,b+3), p2->(b+4,b+5), p3->(b+6,b+7).

    // ---- K-split reduce via smem (buffer 0 is free: last compute used buffer 1) ----
    u64* ps = (u64*)s_act4;           // [r][9] padded: 128*9 u64
    u64* zs = ps + 128 * 9;           // [c][65] padded: 16*65 u64
    if (ks == 1) {
        #pragma unroll
        for (int a = 0; a < 8; a++) ps[r * 9 + a] = acc[a];
    }
    __syncthreads();
    if (ks == 0) {
        #pragma unroll
        for (int a = 0; a < 8; a++) {
            u64 s = add2(acc[a], ps[r * 9 + a]);
            int q = a >> 1, cc = a & 1;
            zs[(2 * ct + cc) * 65 + 4 * bt + q] = s;   // zs[c][bp], bp = batch pair
        }
    }
    __syncthreads();

    // ---- gate math: thread -> (jj = tid&3, bp = tid>>2), 2 batches each ----
    {
        const int jj = tid & 3;
        const int bp = tid >> 2;      // 0..63
        u64 zi_ = zs[(jj * 4 + 0) * 65 + bp];
        u64 zf_ = zs[(jj * 4 + 1) * 65 + bp];
        u64 zg_ = zs[(jj * 4 + 2) * 65 + bp];
        u64 zo_ = zs[(jj * 4 + 3) * 65 + bp];
        float2 zi = up2(zi_), zf = up2(zf_), zg = up2(zg_), zo = up2(zo_);

        const int j = j0 + jj;
        const float bi = bias[j];
        const float bf = bias[H_ + j];
        const float bg = bias[2 * H_ + j];
        const float bo = bias[3 * H_ + j];

        float* cs = cstate + jj * 128 + 2 * bp;

        float siA = fsig(zi.x + bi), sfA = fsig(zf.x + bf);
        float tgA = ftanh(zg.x + bg), soA = fsig(zo.x + bo);
        float cnA = sfA * cs[0] + siA * tgA;
        cs[0] = cnA;
        float hA = soA * ftanh(cnA);

        float siB = fsig(zi.y + bi), sfB = fsig(zf.y + bf);
        float tgB = ftanh(zg.y + bg), soB = fsig(zo.y + bo);
        float cnB = sfB * cs[1] + siB * tgB;
        cs[1] = cnB;
        float hB = soB * ftanh(cnB);

        *(float2*)(hout + j * 128 + 2 * bp) = make_float2(hA, hB);
    }
    __syncthreads();   // protect zs/ps before next phase's prefetch into buffer 0
}

// ---------------- persistent main kernel: 128 CTAs x 256 threads ----------------
__global__ void __launch_bounds__(256, 1)
lstm_main(const float* __restrict__ b0g,
          const float* __restrict__ b1g,
          const float* __restrict__ Wp,
          const float* __restrict__ bp,
          float* __restrict__ out)
{
    extern __shared__ float smem[];
    float* s_w0  = smem;                    // 768*16   = 12288 floats
    float* s_w1  = s_w0 + 768 * 16;         // 1024*16  = 16384 floats
    float* s_act = s_w1 + 1024 * 16;        // 2*64*128 = 16384 floats
    float* s_c0  = s_act + 16384;           // 512
    float* s_c1  = s_c0 + 512;              // 512
    // total = 12288+16384+16384+512+512 = 46080 floats = 184320 bytes

    const int tid = threadIdx.x;
    const unsigned G = gridDim.x;
    const int jt = blockIdx.x;
    const int j0 = jt * 4;
    const int ks = tid >> 7;      // 0..1
    const int r  = tid & 127;
    const int bt = r >> 3;        // 0..15 (8 batches)
    const int ct = r & 7;         // 0..7  (2 cols)

    // preload packed weights into smem (resident for entire kernel)
    {
        const float4* w0s = (const float4*)g_W0p + (size_t)jt * 768 * 4;
        const float4* w1s = (const float4*)g_W1p + (size_t)jt * 1024 * 4;
        float4* d0 = (float4*)s_w0;
        float4* d1 = (float4*)s_w1;
        for (int i = tid; i < 768 * 4; i += 256) d0[i] = w0s[i];
        for (int i = tid; i < 1024 * 4; i += 256) d1[i] = w1s[i];
    }
    for (int i = tid; i < 512; i += 256) { s_c0[i] = 0.f; s_c1[i] = 0.f; }
    __syncthreads();

    float4* s_act4 = (float4*)s_act;
    const u64* s_w064 = (const u64*)s_w0;
    const u64* s_w164 = (const u64*)s_w1;

    for (int t = 0; t < S_; t++) {
        const int cur = t & 1, prv = cur ^ 1;

        // L0: act = [x_t (256 rows) | h0_prev (512 rows)], 12 chunks (4 from x)
        do_phase((const float4*)(g_xT + (size_t)t * D_ * B_),
                 (const float4*)g_h0[prv], t == 0, 12, 4,
                 s_w064, s_act4, s_c0, g_h0[cur], b0g,
                 tid, ks, r, bt, ct, j0);

        grid_sync(G);   // h0(t) visible to all CTAs; orders h1(t-1)->h1(t) too

        // L1: act = [h0_cur (512) | h1_prev (512)], 16 chunks (8 from h0)
        do_phase((const float4*)g_h0[cur],
                 (const float4*)g_h1[prv], t == 0, 16, 8,
                 s_w164, s_act4, s_c1, g_h1[cur], b1g,
                 tid, ks, r, bt, ct, j0);
        // next step's L0 grid_sync orders L1(t) -> L1(t+1)
    }

    grid_sync(G);

    // ---- projection: out[b][m] = sum_k h1T[k][b] * Wp[k][m] + bp[m] ----
    {
        const float* h1f = g_h1[1];   // t = 511 -> cur = 1
        int mstart = jt * 10;
        int mend = mstart + 10; if (mend > ODIM) mend = ODIM;
        int b  = tid & 127;
        int mq = tid >> 7;            // 0..1
        for (int m = mstart + mq; m < mend; m += 2) {
            float acc = bp[m];
            #pragma unroll 4
            for (int k = 0; k < H_; k += 4) {
                acc += h1f[(k + 0) * 128 + b] * Wp[(k + 0) * ODIM + m];
                acc += h1f[(k + 1) * 128 + b] * Wp[(k + 1) * ODIM + m];
                acc += h1f[(k + 2) * 128 + b] * Wp[(k + 2) * ODIM + m];
                acc += h1f[(k + 3) * 128 + b] * Wp[(k + 3) * ODIM + m];
            }
            out[b * ODIM + m] = acc;
        }
    }
}

// ---------------- entry ----------------
extern "C" void kernel_launch(void* const* d_in, const int* in_sizes, int n_in,
                              void* d_out, int out_size)
{
    const float* x  = (const float*)d_in[0];
    const float* W0 = (const float*)d_in[1];
    const float* b0 = (const float*)d_in[2];
    const float* W1 = (const float*)d_in[3];
    const float* b1 = (const float*)d_in[4];
    const float* Wp = (const float*)d_in[5];
    const float* bp = (const float*)d_in[6];
    float* out = (float*)d_out;

    cudaFuncSetAttribute(lstm_main, cudaFuncAttributeMaxDynamicSharedMemorySize, 184320);

    prep_kernel<<<2048, 256>>>(x, W0, W1);
    lstm_main<<<128, 256, 184320>>>(b0, b1, Wp, bp, out);
}